// round 11
// baseline (speedup 1.0000x reference)
#include <cuda_runtime.h>
#include <cuda_fp16.h>
#include <cstdint>

#define HEADS 32
#define D 64
#define S 8192

#define CHUNKS 16
#define CH_S (S / CHUNKS)   // 512
#define SUBS 64
#define B_NIT (CH_S / SUBS) // 8
#define C_ST 128
#define C_TPC 4

// ---------------- scratch ----------------
__device__ __align__(16) float g_ctx_acc[HEADS * D * D];    // 512 KB accumulators
__device__ __align__(16) float g_rsum_acc[HEADS * D];
__device__ __align__(16) __half g_ctxT[HEADS * D * D];      // [h][j][i]

// ---------------- helpers ----------------
__device__ __forceinline__ uint32_t smem_u32(const void* p) {
    uint32_t a;
    asm("{ .reg .u64 t; cvta.to.shared.u64 t, %1; cvt.u32.u64 %0, t; }" : "=r"(a) : "l"(p));
    return a;
}
#define SW(o) ((uint32_t)(o) ^ ((((uint32_t)(o)) >> 3) & 0x70))

__device__ __forceinline__ void ldmx4(uint32_t* r, uint32_t addr) {
    asm volatile("ldmatrix.sync.aligned.m8n8.x4.shared.b16 {%0,%1,%2,%3}, [%4];"
                 : "=r"(r[0]), "=r"(r[1]), "=r"(r[2]), "=r"(r[3]) : "r"(addr));
}
__device__ __forceinline__ void ldmx4t(uint32_t* r, uint32_t addr) {
    asm volatile("ldmatrix.sync.aligned.m8n8.x4.trans.shared.b16 {%0,%1,%2,%3}, [%4];"
                 : "=r"(r[0]), "=r"(r[1]), "=r"(r[2]), "=r"(r[3]) : "r"(addr));
}
__device__ __forceinline__ void mma16816(float* c, const uint32_t* a,
                                         uint32_t b0, uint32_t b1) {
    asm volatile(
        "mma.sync.aligned.m16n8k16.row.col.f32.f16.f16.f32 "
        "{%0,%1,%2,%3}, {%4,%5,%6,%7}, {%8,%9}, {%0,%1,%2,%3};"
        : "+f"(c[0]), "+f"(c[1]), "+f"(c[2]), "+f"(c[3])
        : "r"(a[0]), "r"(a[1]), "r"(a[2]), "r"(a[3]), "r"(b0), "r"(b1));
}
__device__ __forceinline__ uint32_t hf2(float x, float y) {
    uint32_t d;
    asm("cvt.rn.f16x2.f32 %0, %1, %2;" : "=r"(d) : "f"(y), "f"(x));
    return d;
}
__device__ __forceinline__ uint2 pack4(float a, float b, float c, float d) {
    uint2 r;
    r.x = hf2(a, b);
    r.y = hf2(c, d);
    return r;
}

// =====================================================================
// Kernel Z: zero the accumulators (graph-deterministic)
// =====================================================================
__global__ void kernelZ() {
    const int i = blockIdx.x * 256 + threadIdx.x;
    ((float4*)g_ctx_acc)[i] = make_float4(0.f, 0.f, 0.f, 0.f);
    if (i < HEADS * D / 4)
        ((float4*)g_rsum_acc)[i] = make_float4(0.f, 0.f, 0.f, 0.f);
}

// =====================================================================
// Kernel B: per (head, chunk=512s): acc[i][j] += sum_s eK[i,s] V[j,s]
// fp16, double-buffered, reg-prefetch, one sync per subtile.
// Epilogue: atomicAdd into g_ctx_acc / g_rsum_acc (L2-resident).
// =====================================================================
#define B_SRS 32768
__global__ void __launch_bounds__(256, 3) kernelB(const float* __restrict__ K,
                                                  const float* __restrict__ V) {
    extern __shared__ __align__(1024) char sm[];
    const uint32_t sb = smem_u32(sm);
    float* sRS = (float*)(sm + B_SRS);
    const int tid = threadIdx.x, lane = tid & 31, wid = tid >> 5;
    const int ch = blockIdx.x, h = blockIdx.y;

    if (tid < 64) sRS[tid] = 0.f;

    const size_t gbase = (size_t)h * D * S + (size_t)ch * CH_S;
    const int wm = wid & 3, wn = wid >> 2;
    const int lr = (lane & 7) + ((lane >> 3) & 1) * 8;
    const int lcs = lane >> 4;

    const float* kp[4];
    const float* vp[4];
    uint32_t so_[4];
    int rrow[4];
    #pragma unroll
    for (int u = 0; u < 4; u++) {
        const int idx = tid + (u << 8);
        const int r = idx >> 4, c4 = idx & 15;
        rrow[u] = r;
        so_[u] = SW(r * 128 + c4 * 8);
        kp[u] = K + gbase + (size_t)r * S + c4 * 4;
        vp[u] = V + gbase + (size_t)r * S + c4 * 4;
    }

    float4 pk[4], pv[4];
    #pragma unroll
    for (int u = 0; u < 4; u++) { pk[u] = *(const float4*)kp[u]; pv[u] = *(const float4*)vp[u]; }

    float rs[4] = {0.f, 0.f, 0.f, 0.f};

    auto transform = [&](uint32_t bb) {
        #pragma unroll
        for (int u = 0; u < 4; u++) {
            float e0 = __expf(pk[u].x), e1 = __expf(pk[u].y);
            float e2 = __expf(pk[u].z), e3 = __expf(pk[u].w);
            rs[u] += (e0 + e1) + (e2 + e3);
            *(uint2*)(sm + bb + so_[u]) = pack4(e0, e1, e2, e3);
            *(uint2*)(sm + bb + 8192 + so_[u]) = pack4(pv[u].x, pv[u].y, pv[u].z, pv[u].w);
        }
    };

    __syncthreads();
    transform(0);

    float acc[4][4] = {};

    for (int t = 0; t < B_NIT; t++) {
        __syncthreads();
        if (t + 1 < B_NIT) {
            const int off = (t + 1) * SUBS;
            #pragma unroll
            for (int u = 0; u < 4; u++) {
                pk[u] = *(const float4*)(kp[u] + off);
                pv[u] = *(const float4*)(vp[u] + off);
            }
        }
        const uint32_t bb = (uint32_t)(t & 1) * 16384;
        #pragma unroll
        for (int ks = 0; ks < 4; ks++) {
            const uint32_t aoff = SW((16 * wm + lr) * 128 + ks * 32 + lcs * 16);
            uint32_t ah[4];
            ldmx4(ah, sb + bb + aoff);
            uint32_t bh[2][4];
            #pragma unroll
            for (int hlf = 0; hlf < 2; hlf++) {
                const uint32_t boff =
                    SW((32 * wn + 16 * hlf + lr) * 128 + ks * 32 + lcs * 16);
                ldmx4(bh[hlf], sb + bb + 8192 + boff);
            }
            #pragma unroll
            for (int nt = 0; nt < 4; nt++) {
                const int hf = nt >> 1, sub = nt & 1;
                mma16816(acc[nt], ah, bh[hf][sub], bh[hf][sub + 2]);
            }
        }
        if (t + 1 < B_NIT) transform((uint32_t)((t + 1) & 1) * 16384);
    }

    #pragma unroll
    for (int u = 0; u < 4; u++) {
        float v = rs[u];
        v += __shfl_xor_sync(~0u, v, 1);
        v += __shfl_xor_sync(~0u, v, 2);
        v += __shfl_xor_sync(~0u, v, 4);
        v += __shfl_xor_sync(~0u, v, 8);
        if ((lane & 15) == 0) atomicAdd(&sRS[rrow[u]], v);
    }
    __syncthreads();

    if (tid < 64) atomicAdd(&g_rsum_acc[h * D + tid], sRS[tid]);

    float* pc = g_ctx_acc + (size_t)h * (D * D);
    const int g8 = lane >> 2, tig = lane & 3;
    #pragma unroll
    for (int nt = 0; nt < 4; nt++) {
        const int j = 32 * wn + 8 * nt + 2 * tig;
        const int i0 = 16 * wm + g8;
        atomicAdd(&pc[i0 * D + j], acc[nt][0]);
        atomicAdd(&pc[i0 * D + j + 1], acc[nt][1]);
        atomicAdd(&pc[(i0 + 8) * D + j], acc[nt][2]);
        atomicAdd(&pc[(i0 + 8) * D + j + 1], acc[nt][3]);
    }
}

// =====================================================================
// Kernel B2: normalize rows, fold 1/8 scale, write transposed fp16 ctx^T
// =====================================================================
__global__ void __launch_bounds__(256) kernelB2() {
    const int h = blockIdx.x, tid = threadIdx.x;
    __shared__ float sinv[D];
    if (tid < D) sinv[tid] = 0.125f / g_rsum_acc[h * D + tid];
    __syncthreads();
    for (int idx = tid; idx < D * D; idx += 256) {
        const int i = idx >> 6, j = idx & 63;
        g_ctxT[h * D * D + j * D + i] =
            __float2half_rn(g_ctx_acc[h * D * D + idx] * sinv[i]);
    }
}

// =====================================================================
// Kernel C: per (head, 4 s-tiles): out[j,s] = colinv[s]*sum_i ctxT[j,i]*EQ[i,s]
// Warp tiling 2x4: warp owns 32 j x 32 s -> ldmatrix 64KB/CTA-tile (was 80KB).
// smem: ctx @0 (8K) | EQ @8K (two 64-s halves of 8K) | csum[4][128] @24K
// =====================================================================
#define C_EQ 8192
#define C_CS 24576
__global__ void __launch_bounds__(256, 3) kernelC(const float* __restrict__ Q,
                                                  float* __restrict__ O) {
    extern __shared__ __align__(1024) char sm[];
    const uint32_t sb = smem_u32(sm);
    const int tid = threadIdx.x, lane = tid & 31, wid = tid >> 5;
    const int stp = blockIdx.x, h = blockIdx.y;

    if (tid < 128)
        ((float4*)(sm + C_CS))[tid] = make_float4(0.f, 0.f, 0.f, 0.f);

    // ctx^T tile (64 x 64 fp16, swizzled copy)
    {
        const uint64_t* src = (const uint64_t*)(g_ctxT + h * D * D);
        #pragma unroll
        for (int u = 0; u < 4; u++) {
            const int idx = tid + (u << 8);
            *(uint64_t*)(sm + SW(idx * 8)) = src[idx];
        }
    }

    const int s4 = tid & 31, iw = tid >> 5;
    const int tsel = s4 >> 4;
    const int srel = (s4 & 15) * 4;
    const float* qt = Q + (size_t)h * D * S + (size_t)stp * (C_TPC * C_ST)
                    + (size_t)iw * S + s4 * 4;

    // warp tiling: wj in {0,1} -> 32 j rows; ws in 0..3 -> 32 s cols
    const int wj = wid & 1, ws = wid >> 1;
    const int lr = (lane & 7) + ((lane >> 3) & 1) * 8;
    const int lcs = lane >> 4;
    const int g8 = lane >> 2, tig = lane & 3;
    const uint32_t eqhalf = C_EQ + (uint32_t)(ws >> 1) * 8192;  // 64-s half base
    const int sw32 = (ws & 1) * 32;                             // s offset in half

    __syncthreads();            // csum + ctx visible

    for (int t = 0; t < C_TPC; t++) {
        // ---- transform: direct LDG -> exp -> STS, csum in regs ----
        float* csum = (float*)(sm + C_CS) + t * 128;
        {
            float cs0 = 0.f, cs1 = 0.f, cs2 = 0.f, cs3 = 0.f;
            const float* qb = qt + t * C_ST;
            #pragma unroll
            for (int u = 0; u < 8; u++) {
                float4 qv = *(const float4*)(qb + (size_t)(8 * u) * S);
                float e0 = __expf(qv.x), e1 = __expf(qv.y);
                float e2 = __expf(qv.z), e3 = __expf(qv.w);
                cs0 += e0; cs1 += e1; cs2 += e2; cs3 += e3;
                const int i = iw + 8 * u;
                *(uint2*)(sm + C_EQ + tsel * 8192 + SW(i * 128 + srel * 2)) =
                    pack4(e0, e1, e2, e3);
            }
            atomicAdd(&csum[s4 * 4 + 0], cs0);
            atomicAdd(&csum[s4 * 4 + 1], cs1);
            atomicAdd(&csum[s4 * 4 + 2], cs2);
            atomicAdd(&csum[s4 * 4 + 3], cs3);
        }
        __syncthreads();        // EQ + csum ready

        // ---- MMA: 2 m16 tiles x 4 n8 tiles x 4 k16 ----
        float acc[2][4][4] = {};
        #pragma unroll
        for (int ks = 0; ks < 4; ks++) {
            uint32_t ah[2][4];
            #pragma unroll
            for (int mt = 0; mt < 2; mt++) {
                const uint32_t aoff =
                    SW((32 * wj + 16 * mt + lr) * 128 + ks * 32 + lcs * 16);
                ldmx4(ah[mt], sb + aoff);
            }
            #pragma unroll
            for (int nb = 0; nb < 2; nb++) {
                const uint32_t boff =
                    SW((ks * 16 + lr) * 128 + (sw32 + nb * 16 + lcs * 8) * 2);
                uint32_t bh[4];
                ldmx4t(bh, sb + eqhalf + boff);
                #pragma unroll
                for (int mt = 0; mt < 2; mt++) {
                    mma16816(acc[mt][2 * nb], ah[mt], bh[0], bh[1]);
                    mma16816(acc[mt][2 * nb + 1], ah[mt], bh[2], bh[3]);
                }
            }
        }

        // ---- epilogue ----
        #pragma unroll
        for (int mt = 0; mt < 2; mt++) {
            #pragma unroll
            for (int nt = 0; nt < 4; nt++) {
                const int sl = 32 * ws + 8 * nt + 2 * tig;
                const float2 cs = *(const float2*)&csum[sl];
                const float ix = __frcp_rn(cs.x), iy = __frcp_rn(cs.y);
                const int j = 32 * wj + 16 * mt + g8;
                const size_t ob = ((size_t)h * D + j) * S
                                + (size_t)stp * (C_TPC * C_ST) + (size_t)t * C_ST + sl;
                float2 v0 = {acc[mt][nt][0] * ix, acc[mt][nt][1] * iy};
                float2 v1 = {acc[mt][nt][2] * ix, acc[mt][nt][3] * iy};
                *(float2*)(O + ob) = v0;
                *(float2*)(O + ob + 8 * S) = v1;
            }
        }
        __syncthreads();        // MMA/epilogue done before EQ overwrite
    }
}

// =====================================================================
extern "C" void kernel_launch(void* const* d_in, const int* in_sizes, int n_in,
                              void* d_out, int out_size) {
    const float* q = (const float*)d_in[0];
    const float* k = (const float*)d_in[1];
    const float* v = (const float*)d_in[2];
    float* o = (float*)d_out;

    const int smemB = B_SRS + 256;        // 33024
    const int smemC = C_CS + 2048;        // 26624
    cudaFuncSetAttribute(kernelB, cudaFuncAttributeMaxDynamicSharedMemorySize, smemB);
    cudaFuncSetAttribute(kernelC, cudaFuncAttributeMaxDynamicSharedMemorySize, smemC);

    kernelZ<<<HEADS * D * D / 4 / 256, 256>>>();
    dim3 gridB(CHUNKS, HEADS);
    kernelB<<<gridB, 256, smemB>>>(k, v);
    kernelB2<<<HEADS, 256>>>();
    dim3 gridC(S / (C_TPC * C_ST), HEADS);
    kernelC<<<gridC, 256, smemC>>>(q, o);
}

// round 12
// speedup vs baseline: 1.3355x; 1.3355x over previous
#include <cuda_runtime.h>
#include <cuda_fp16.h>
#include <cstdint>

#define HEADS 32
#define D 64
#define S 8192

#define CHUNKS 16
#define CH_S (S / CHUNKS)   // 512
#define SUBS 64
#define B_NIT (CH_S / SUBS) // 8
#define C_ST 128
#define C_TPC 4

// ---------------- scratch ----------------
__device__ __align__(16) float g_ctx_acc[HEADS * D * D];    // 512 KB accumulators
__device__ __align__(16) float g_rsum_acc[HEADS * D];

// ---------------- helpers ----------------
__device__ __forceinline__ uint32_t smem_u32(const void* p) {
    uint32_t a;
    asm("{ .reg .u64 t; cvta.to.shared.u64 t, %1; cvt.u32.u64 %0, t; }" : "=r"(a) : "l"(p));
    return a;
}
#define SW(o) ((uint32_t)(o) ^ ((((uint32_t)(o)) >> 3) & 0x70))

__device__ __forceinline__ void ldmx4(uint32_t* r, uint32_t addr) {
    asm volatile("ldmatrix.sync.aligned.m8n8.x4.shared.b16 {%0,%1,%2,%3}, [%4];"
                 : "=r"(r[0]), "=r"(r[1]), "=r"(r[2]), "=r"(r[3]) : "r"(addr));
}
__device__ __forceinline__ void ldmx4t(uint32_t* r, uint32_t addr) {
    asm volatile("ldmatrix.sync.aligned.m8n8.x4.trans.shared.b16 {%0,%1,%2,%3}, [%4];"
                 : "=r"(r[0]), "=r"(r[1]), "=r"(r[2]), "=r"(r[3]) : "r"(addr));
}
__device__ __forceinline__ void mma16816(float* c, const uint32_t* a,
                                         uint32_t b0, uint32_t b1) {
    asm volatile(
        "mma.sync.aligned.m16n8k16.row.col.f32.f16.f16.f32 "
        "{%0,%1,%2,%3}, {%4,%5,%6,%7}, {%8,%9}, {%0,%1,%2,%3};"
        : "+f"(c[0]), "+f"(c[1]), "+f"(c[2]), "+f"(c[3])
        : "r"(a[0]), "r"(a[1]), "r"(a[2]), "r"(a[3]), "r"(b0), "r"(b1));
}
__device__ __forceinline__ uint32_t hf2(float x, float y) {
    uint32_t d;
    asm("cvt.rn.f16x2.f32 %0, %1, %2;" : "=r"(d) : "f"(y), "f"(x));
    return d;
}
__device__ __forceinline__ uint2 pack4(float a, float b, float c, float d) {
    uint2 r;
    r.x = hf2(a, b);
    r.y = hf2(c, d);
    return r;
}

// =====================================================================
// Kernel Z: zero the accumulators (graph-deterministic)
// =====================================================================
__global__ void kernelZ() {
    const int i = blockIdx.x * 256 + threadIdx.x;
    ((float4*)g_ctx_acc)[i] = make_float4(0.f, 0.f, 0.f, 0.f);
    if (i < HEADS * D / 4)
        ((float4*)g_rsum_acc)[i] = make_float4(0.f, 0.f, 0.f, 0.f);
}

// =====================================================================
// Kernel B: per (head, chunk=512s): acc[i][j] += sum_s eK[i,s] V[j,s]
// fp16, double-buffered, reg-prefetch, one sync per subtile.
// Epilogue: atomicAdd into g_ctx_acc / g_rsum_acc (L2-resident).
// =====================================================================
#define B_SRS 32768
__global__ void __launch_bounds__(256, 3) kernelB(const float* __restrict__ K,
                                                  const float* __restrict__ V) {
    extern __shared__ __align__(1024) char sm[];
    const uint32_t sb = smem_u32(sm);
    float* sRS = (float*)(sm + B_SRS);
    const int tid = threadIdx.x, lane = tid & 31, wid = tid >> 5;
    const int ch = blockIdx.x, h = blockIdx.y;

    if (tid < 64) sRS[tid] = 0.f;

    const size_t gbase = (size_t)h * D * S + (size_t)ch * CH_S;
    const int wm = wid & 3, wn = wid >> 2;
    const int lr = (lane & 7) + ((lane >> 3) & 1) * 8;
    const int lcs = lane >> 4;

    const float* kp[4];
    const float* vp[4];
    uint32_t so_[4];
    int rrow[4];
    #pragma unroll
    for (int u = 0; u < 4; u++) {
        const int idx = tid + (u << 8);
        const int r = idx >> 4, c4 = idx & 15;
        rrow[u] = r;
        so_[u] = SW(r * 128 + c4 * 8);
        kp[u] = K + gbase + (size_t)r * S + c4 * 4;
        vp[u] = V + gbase + (size_t)r * S + c4 * 4;
    }

    float4 pk[4], pv[4];
    #pragma unroll
    for (int u = 0; u < 4; u++) { pk[u] = *(const float4*)kp[u]; pv[u] = *(const float4*)vp[u]; }

    float rs[4] = {0.f, 0.f, 0.f, 0.f};

    auto transform = [&](uint32_t bb) {
        #pragma unroll
        for (int u = 0; u < 4; u++) {
            float e0 = __expf(pk[u].x), e1 = __expf(pk[u].y);
            float e2 = __expf(pk[u].z), e3 = __expf(pk[u].w);
            rs[u] += (e0 + e1) + (e2 + e3);
            *(uint2*)(sm + bb + so_[u]) = pack4(e0, e1, e2, e3);
            *(uint2*)(sm + bb + 8192 + so_[u]) = pack4(pv[u].x, pv[u].y, pv[u].z, pv[u].w);
        }
    };

    __syncthreads();
    transform(0);

    float acc[4][4] = {};

    for (int t = 0; t < B_NIT; t++) {
        __syncthreads();
        if (t + 1 < B_NIT) {
            const int off = (t + 1) * SUBS;
            #pragma unroll
            for (int u = 0; u < 4; u++) {
                pk[u] = *(const float4*)(kp[u] + off);
                pv[u] = *(const float4*)(vp[u] + off);
            }
        }
        const uint32_t bb = (uint32_t)(t & 1) * 16384;
        #pragma unroll
        for (int ks = 0; ks < 4; ks++) {
            const uint32_t aoff = SW((16 * wm + lr) * 128 + ks * 32 + lcs * 16);
            uint32_t ah[4];
            ldmx4(ah, sb + bb + aoff);
            uint32_t bh[2][4];
            #pragma unroll
            for (int hlf = 0; hlf < 2; hlf++) {
                const uint32_t boff =
                    SW((32 * wn + 16 * hlf + lr) * 128 + ks * 32 + lcs * 16);
                ldmx4(bh[hlf], sb + bb + 8192 + boff);
            }
            #pragma unroll
            for (int nt = 0; nt < 4; nt++) {
                const int hf = nt >> 1, sub = nt & 1;
                mma16816(acc[nt], ah, bh[hf][sub], bh[hf][sub + 2]);
            }
        }
        if (t + 1 < B_NIT) transform((uint32_t)((t + 1) & 1) * 16384);
    }

    #pragma unroll
    for (int u = 0; u < 4; u++) {
        float v = rs[u];
        v += __shfl_xor_sync(~0u, v, 1);
        v += __shfl_xor_sync(~0u, v, 2);
        v += __shfl_xor_sync(~0u, v, 4);
        v += __shfl_xor_sync(~0u, v, 8);
        if ((lane & 15) == 0) atomicAdd(&sRS[rrow[u]], v);
    }
    __syncthreads();

    if (tid < 64) atomicAdd(&g_rsum_acc[h * D + tid], sRS[tid]);

    float* pc = g_ctx_acc + (size_t)h * (D * D);
    const int g8 = lane >> 2, tig = lane & 3;
    #pragma unroll
    for (int nt = 0; nt < 4; nt++) {
        const int j = 32 * wn + 8 * nt + 2 * tig;
        const int i0 = 16 * wm + g8;
        atomicAdd(&pc[i0 * D + j], acc[nt][0]);
        atomicAdd(&pc[i0 * D + j + 1], acc[nt][1]);
        atomicAdd(&pc[(i0 + 8) * D + j], acc[nt][2]);
        atomicAdd(&pc[(i0 + 8) * D + j + 1], acc[nt][3]);
    }
}

// =====================================================================
// Kernel C: per (head, 4 s-tiles): out[j,s] = colinv[s]*sum_i ctxT[j,i]*EQ[i,s]
// Prologue absorbs old kernelB2: reads g_ctx_acc/g_rsum_acc, normalizes,
// writes fp16 ctx^T straight into smem (no g_ctxT global).
// Mainloop = proven R8 tiling (warp = 16 j x 64 s).
// smem: ctx @0 (8K) | EQ @8K (16K: two 64-s halves) | csum[4][128] @24K | sinv @26624
// =====================================================================
#define C_EQ 8192
#define C_CS 24576
#define C_SINV 26624
__global__ void __launch_bounds__(256, 3) kernelC(const float* __restrict__ Q,
                                                  float* __restrict__ O) {
    extern __shared__ __align__(1024) char sm[];
    const uint32_t sb = smem_u32(sm);
    const int tid = threadIdx.x, lane = tid & 31, wid = tid >> 5;
    const int stp = blockIdx.x, h = blockIdx.y;

    float* sinv = (float*)(sm + C_SINV);
    if (tid < 64) sinv[tid] = 0.125f / g_rsum_acc[h * D + tid];
    if (tid < 128)
        ((float4*)(sm + C_CS))[tid] = make_float4(0.f, 0.f, 0.f, 0.f);
    __syncthreads();            // sinv + csum visible

    // normalize ctx_acc -> fp16 ctx^T smem tile (swizzled, 128B rows of 64 i)
    {
        const int j40 = (tid & 15) * 4;     // 4 consecutive j per thread
        const int ib = tid >> 4;            // i base 0..15
        #pragma unroll
        for (int k = 0; k < 4; k++) {
            const int i = ib + 16 * k;
            float4 v = *(const float4*)(g_ctx_acc + (size_t)h * (D * D) + i * D + j40);
            const float s = sinv[i];
            *(__half*)(sm + SW((j40 + 0) * 128 + i * 2)) = __float2half_rn(v.x * s);
            *(__half*)(sm + SW((j40 + 1) * 128 + i * 2)) = __float2half_rn(v.y * s);
            *(__half*)(sm + SW((j40 + 2) * 128 + i * 2)) = __float2half_rn(v.z * s);
            *(__half*)(sm + SW((j40 + 3) * 128 + i * 2)) = __float2half_rn(v.w * s);
        }
    }

    const int s4 = tid & 31, iw = tid >> 5;
    const int tsel = s4 >> 4;
    const int srel = (s4 & 15) * 4;
    const float* qt = Q + (size_t)h * D * S + (size_t)stp * (C_TPC * C_ST)
                    + (size_t)iw * S + s4 * 4;

    const int wm = wid & 3, wn = wid >> 2;
    const int lr = (lane & 7) + ((lane >> 3) & 1) * 8;
    const int lcs = lane >> 4;
    const int g8 = lane >> 2, tig = lane & 3;

    __syncthreads();            // ctx tile ready

    for (int t = 0; t < C_TPC; t++) {
        // ---- transform: direct LDG -> exp -> STS, csum in regs ----
        float* csum = (float*)(sm + C_CS) + t * 128;
        {
            float cs0 = 0.f, cs1 = 0.f, cs2 = 0.f, cs3 = 0.f;
            const float* qb = qt + t * C_ST;
            #pragma unroll
            for (int u = 0; u < 8; u++) {
                float4 qv = *(const float4*)(qb + (size_t)(8 * u) * S);
                float e0 = __expf(qv.x), e1 = __expf(qv.y);
                float e2 = __expf(qv.z), e3 = __expf(qv.w);
                cs0 += e0; cs1 += e1; cs2 += e2; cs3 += e3;
                const int i = iw + 8 * u;
                *(uint2*)(sm + C_EQ + tsel * 8192 + SW(i * 128 + srel * 2)) =
                    pack4(e0, e1, e2, e3);
            }
            atomicAdd(&csum[s4 * 4 + 0], cs0);
            atomicAdd(&csum[s4 * 4 + 1], cs1);
            atomicAdd(&csum[s4 * 4 + 2], cs2);
            atomicAdd(&csum[s4 * 4 + 3], cs3);
        }
        __syncthreads();        // EQ + csum ready

        // ---- MMA (R8 layout: warp = 16 j x 64 s) ----
        float acc[8][4] = {};
        #pragma unroll
        for (int ks = 0; ks < 4; ks++) {
            const uint32_t aoff = SW((16 * wm + lr) * 128 + ks * 32 + lcs * 16);
            uint32_t ah[4];
            ldmx4(ah, sb + aoff);
            #pragma unroll
            for (int nb = 0; nb < 4; nb++) {
                const uint32_t boff = SW((ks * 16 + lr) * 128 + (nb * 16 + lcs * 8) * 2);
                uint32_t bh[4];
                ldmx4t(bh, sb + C_EQ + wn * 8192 + boff);
                mma16816(acc[2 * nb], ah, bh[0], bh[1]);
                mma16816(acc[2 * nb + 1], ah, bh[2], bh[3]);
            }
        }

        // ---- epilogue ----
        #pragma unroll
        for (int nt = 0; nt < 8; nt++) {
            const int sl = wn * 64 + nt * 8 + 2 * tig;
            const float2 cs = *(const float2*)&csum[sl];
            const float ix = __frcp_rn(cs.x), iy = __frcp_rn(cs.y);
            const int j = 16 * wm + g8;
            const size_t ob = ((size_t)h * D + j) * S
                            + (size_t)stp * (C_TPC * C_ST) + (size_t)t * C_ST + sl;
            float2 v0 = {acc[nt][0] * ix, acc[nt][1] * iy};
            float2 v1 = {acc[nt][2] * ix, acc[nt][3] * iy};
            *(float2*)(O + ob) = v0;
            *(float2*)(O + ob + 8 * S) = v1;
        }
        __syncthreads();        // MMA/epilogue done before EQ overwrite
    }
}

// =====================================================================
extern "C" void kernel_launch(void* const* d_in, const int* in_sizes, int n_in,
                              void* d_out, int out_size) {
    const float* q = (const float*)d_in[0];
    const float* k = (const float*)d_in[1];
    const float* v = (const float*)d_in[2];
    float* o = (float*)d_out;

    const int smemB = B_SRS + 256;        // 33024
    const int smemC = C_SINV + 256;       // 26880
    cudaFuncSetAttribute(kernelB, cudaFuncAttributeMaxDynamicSharedMemorySize, smemB);
    cudaFuncSetAttribute(kernelC, cudaFuncAttributeMaxDynamicSharedMemorySize, smemC);

    kernelZ<<<HEADS * D * D / 4 / 256, 256>>>();
    dim3 gridB(CHUNKS, HEADS);
    kernelB<<<gridB, 256, smemB>>>(k, v);
    dim3 gridC(S / (C_TPC * C_ST), HEADS);
    kernelC<<<gridC, 256, smemC>>>(q, o);
}

// round 13
// speedup vs baseline: 1.3718x; 1.0272x over previous
#include <cuda_runtime.h>
#include <cuda_fp16.h>
#include <cstdint>

#define HEADS 32
#define D 64
#define S 8192

#define CHUNKS 16
#define CH_S (S / CHUNKS)   // 512
#define SUBS 64
#define B_NIT (CH_S / SUBS) // 8
#define C_ST 128
#define C_TPC 4
#define C_CTAS_PER_HEAD (S / (C_TPC * C_ST))   // 16

// ---------------- scratch ----------------
// Zero-initialized at module load; kernelC re-zeroes after consumption,
// so every launch (first call and graph replays) sees zeros.
__device__ __align__(16) float g_ctx_acc[HEADS * D * D];    // 512 KB accumulators
__device__ __align__(16) float g_rsum_acc[HEADS * D];
__device__ int g_cnt[HEADS];                                // per-head arrival counters

// ---------------- helpers ----------------
__device__ __forceinline__ uint32_t smem_u32(const void* p) {
    uint32_t a;
    asm("{ .reg .u64 t; cvta.to.shared.u64 t, %1; cvt.u32.u64 %0, t; }" : "=r"(a) : "l"(p));
    return a;
}
#define SW(o) ((uint32_t)(o) ^ ((((uint32_t)(o)) >> 3) & 0x70))

__device__ __forceinline__ void ldmx4(uint32_t* r, uint32_t addr) {
    asm volatile("ldmatrix.sync.aligned.m8n8.x4.shared.b16 {%0,%1,%2,%3}, [%4];"
                 : "=r"(r[0]), "=r"(r[1]), "=r"(r[2]), "=r"(r[3]) : "r"(addr));
}
__device__ __forceinline__ void ldmx4t(uint32_t* r, uint32_t addr) {
    asm volatile("ldmatrix.sync.aligned.m8n8.x4.trans.shared.b16 {%0,%1,%2,%3}, [%4];"
                 : "=r"(r[0]), "=r"(r[1]), "=r"(r[2]), "=r"(r[3]) : "r"(addr));
}
__device__ __forceinline__ void mma16816(float* c, const uint32_t* a,
                                         uint32_t b0, uint32_t b1) {
    asm volatile(
        "mma.sync.aligned.m16n8k16.row.col.f32.f16.f16.f32 "
        "{%0,%1,%2,%3}, {%4,%5,%6,%7}, {%8,%9}, {%0,%1,%2,%3};"
        : "+f"(c[0]), "+f"(c[1]), "+f"(c[2]), "+f"(c[3])
        : "r"(a[0]), "r"(a[1]), "r"(a[2]), "r"(a[3]), "r"(b0), "r"(b1));
}
__device__ __forceinline__ uint32_t hf2(float x, float y) {
    uint32_t d;
    asm("cvt.rn.f16x2.f32 %0, %1, %2;" : "=r"(d) : "f"(y), "f"(x));
    return d;
}
__device__ __forceinline__ uint2 pack4(float a, float b, float c, float d) {
    uint2 r;
    r.x = hf2(a, b);
    r.y = hf2(c, d);
    return r;
}

// =====================================================================
// Kernel B: per (head, chunk=512s): acc[i][j] += sum_s eK[i,s] V[j,s]
// fp16, double-buffered, reg-prefetch, one sync per subtile.
// Epilogue: atomicAdd into g_ctx_acc / g_rsum_acc (L2-resident).
// =====================================================================
#define B_SRS 32768
__global__ void __launch_bounds__(256, 3) kernelB(const float* __restrict__ K,
                                                  const float* __restrict__ V) {
    extern __shared__ __align__(1024) char sm[];
    const uint32_t sb = smem_u32(sm);
    float* sRS = (float*)(sm + B_SRS);
    const int tid = threadIdx.x, lane = tid & 31, wid = tid >> 5;
    const int ch = blockIdx.x, h = blockIdx.y;

    if (tid < 64) sRS[tid] = 0.f;

    const size_t gbase = (size_t)h * D * S + (size_t)ch * CH_S;
    const int wm = wid & 3, wn = wid >> 2;
    const int lr = (lane & 7) + ((lane >> 3) & 1) * 8;
    const int lcs = lane >> 4;

    const float* kp[4];
    const float* vp[4];
    uint32_t so_[4];
    int rrow[4];
    #pragma unroll
    for (int u = 0; u < 4; u++) {
        const int idx = tid + (u << 8);
        const int r = idx >> 4, c4 = idx & 15;
        rrow[u] = r;
        so_[u] = SW(r * 128 + c4 * 8);
        kp[u] = K + gbase + (size_t)r * S + c4 * 4;
        vp[u] = V + gbase + (size_t)r * S + c4 * 4;
    }

    float4 pk[4], pv[4];
    #pragma unroll
    for (int u = 0; u < 4; u++) { pk[u] = *(const float4*)kp[u]; pv[u] = *(const float4*)vp[u]; }

    float rs[4] = {0.f, 0.f, 0.f, 0.f};

    auto transform = [&](uint32_t bb) {
        #pragma unroll
        for (int u = 0; u < 4; u++) {
            float e0 = __expf(pk[u].x), e1 = __expf(pk[u].y);
            float e2 = __expf(pk[u].z), e3 = __expf(pk[u].w);
            rs[u] += (e0 + e1) + (e2 + e3);
            *(uint2*)(sm + bb + so_[u]) = pack4(e0, e1, e2, e3);
            *(uint2*)(sm + bb + 8192 + so_[u]) = pack4(pv[u].x, pv[u].y, pv[u].z, pv[u].w);
        }
    };

    __syncthreads();
    transform(0);

    float acc[4][4] = {};

    for (int t = 0; t < B_NIT; t++) {
        __syncthreads();
        if (t + 1 < B_NIT) {
            const int off = (t + 1) * SUBS;
            #pragma unroll
            for (int u = 0; u < 4; u++) {
                pk[u] = *(const float4*)(kp[u] + off);
                pv[u] = *(const float4*)(vp[u] + off);
            }
        }
        const uint32_t bb = (uint32_t)(t & 1) * 16384;
        #pragma unroll
        for (int ks = 0; ks < 4; ks++) {
            const uint32_t aoff = SW((16 * wm + lr) * 128 + ks * 32 + lcs * 16);
            uint32_t ah[4];
            ldmx4(ah, sb + bb + aoff);
            uint32_t bh[2][4];
            #pragma unroll
            for (int hlf = 0; hlf < 2; hlf++) {
                const uint32_t boff =
                    SW((32 * wn + 16 * hlf + lr) * 128 + ks * 32 + lcs * 16);
                ldmx4(bh[hlf], sb + bb + 8192 + boff);
            }
            #pragma unroll
            for (int nt = 0; nt < 4; nt++) {
                const int hf = nt >> 1, sub = nt & 1;
                mma16816(acc[nt], ah, bh[hf][sub], bh[hf][sub + 2]);
            }
        }
        if (t + 1 < B_NIT) transform((uint32_t)((t + 1) & 1) * 16384);
    }

    #pragma unroll
    for (int u = 0; u < 4; u++) {
        float v = rs[u];
        v += __shfl_xor_sync(~0u, v, 1);
        v += __shfl_xor_sync(~0u, v, 2);
        v += __shfl_xor_sync(~0u, v, 4);
        v += __shfl_xor_sync(~0u, v, 8);
        if ((lane & 15) == 0) atomicAdd(&sRS[rrow[u]], v);
    }
    __syncthreads();

    if (tid < 64) atomicAdd(&g_rsum_acc[h * D + tid], sRS[tid]);

    float* pc = g_ctx_acc + (size_t)h * (D * D);
    const int g8 = lane >> 2, tig = lane & 3;
    #pragma unroll
    for (int nt = 0; nt < 4; nt++) {
        const int j = 32 * wn + 8 * nt + 2 * tig;
        const int i0 = 16 * wm + g8;
        atomicAdd(&pc[i0 * D + j], acc[nt][0]);
        atomicAdd(&pc[i0 * D + j + 1], acc[nt][1]);
        atomicAdd(&pc[(i0 + 8) * D + j], acc[nt][2]);
        atomicAdd(&pc[(i0 + 8) * D + j + 1], acc[nt][3]);
    }
}

// =====================================================================
// Kernel C: per (head, 4 s-tiles): out[j,s] = colinv[s]*sum_i ctxT[j,i]*EQ[i,s]
// Prologue: normalize g_ctx_acc -> fp16 ctx^T in smem (absorbed B2).
// Self-cleaning: last CTA per head (arrival counter) re-zeroes that head's
// accumulators + counter after ALL 16 CTAs have consumed them.
// Mainloop = proven R8 tiling (warp = 16 j x 64 s).
// smem: ctx @0 (8K) | EQ @8K (16K) | csum[4][128] @24K | sinv @26624
// =====================================================================
#define C_EQ 8192
#define C_CS 24576
#define C_SINV 26624
__global__ void __launch_bounds__(256, 3) kernelC(const float* __restrict__ Q,
                                                  float* __restrict__ O) {
    extern __shared__ __align__(1024) char sm[];
    __shared__ int zflag;
    const uint32_t sb = smem_u32(sm);
    const int tid = threadIdx.x, lane = tid & 31, wid = tid >> 5;
    const int stp = blockIdx.x, h = blockIdx.y;

    float* sinv = (float*)(sm + C_SINV);
    if (tid < 64) sinv[tid] = 0.125f / g_rsum_acc[h * D + tid];
    if (tid < 128)
        ((float4*)(sm + C_CS))[tid] = make_float4(0.f, 0.f, 0.f, 0.f);
    __syncthreads();            // sinv + csum visible

    // normalize ctx_acc -> fp16 ctx^T smem tile (swizzled, 128B rows of 64 i)
    {
        const int j40 = (tid & 15) * 4;     // 4 consecutive j per thread
        const int ib = tid >> 4;            // i base 0..15
        #pragma unroll
        for (int k = 0; k < 4; k++) {
            const int i = ib + 16 * k;
            float4 v = *(const float4*)(g_ctx_acc + (size_t)h * (D * D) + i * D + j40);
            const float s = sinv[i];
            *(__half*)(sm + SW((j40 + 0) * 128 + i * 2)) = __float2half_rn(v.x * s);
            *(__half*)(sm + SW((j40 + 1) * 128 + i * 2)) = __float2half_rn(v.y * s);
            *(__half*)(sm + SW((j40 + 2) * 128 + i * 2)) = __float2half_rn(v.z * s);
            *(__half*)(sm + SW((j40 + 3) * 128 + i * 2)) = __float2half_rn(v.w * s);
        }
    }
    __syncthreads();            // ctx tile ready; this CTA's accumulator reads done

    // ---- self-cleaning: last CTA of this head zeroes the accumulators ----
    if (tid == 0) {
        const int old = atomicAdd(&g_cnt[h], 1);
        zflag = (old == C_CTAS_PER_HEAD - 1);
    }
    __syncthreads();
    if (zflag) {
        float4* pz = (float4*)(g_ctx_acc + (size_t)h * (D * D));
        #pragma unroll
        for (int u = 0; u < D * D / 4 / 256; u++)
            pz[tid + u * 256] = make_float4(0.f, 0.f, 0.f, 0.f);
        if (tid < D / 4)
            ((float4*)(g_rsum_acc + h * D))[tid] = make_float4(0.f, 0.f, 0.f, 0.f);
        if (tid == 0) g_cnt[h] = 0;
    }

    const int s4 = tid & 31, iw = tid >> 5;
    const int tsel = s4 >> 4;
    const int srel = (s4 & 15) * 4;
    const float* qt = Q + (size_t)h * D * S + (size_t)stp * (C_TPC * C_ST)
                    + (size_t)iw * S + s4 * 4;

    const int wm = wid & 3, wn = wid >> 2;
    const int lr = (lane & 7) + ((lane >> 3) & 1) * 8;
    const int lcs = lane >> 4;
    const int g8 = lane >> 2, tig = lane & 3;

    for (int t = 0; t < C_TPC; t++) {
        // ---- transform: direct LDG -> exp -> STS, csum in regs ----
        float* csum = (float*)(sm + C_CS) + t * 128;
        {
            float cs0 = 0.f, cs1 = 0.f, cs2 = 0.f, cs3 = 0.f;
            const float* qb = qt + t * C_ST;
            #pragma unroll
            for (int u = 0; u < 8; u++) {
                float4 qv = *(const float4*)(qb + (size_t)(8 * u) * S);
                float e0 = __expf(qv.x), e1 = __expf(qv.y);
                float e2 = __expf(qv.z), e3 = __expf(qv.w);
                cs0 += e0; cs1 += e1; cs2 += e2; cs3 += e3;
                const int i = iw + 8 * u;
                *(uint2*)(sm + C_EQ + tsel * 8192 + SW(i * 128 + srel * 2)) =
                    pack4(e0, e1, e2, e3);
            }
            atomicAdd(&csum[s4 * 4 + 0], cs0);
            atomicAdd(&csum[s4 * 4 + 1], cs1);
            atomicAdd(&csum[s4 * 4 + 2], cs2);
            atomicAdd(&csum[s4 * 4 + 3], cs3);
        }
        __syncthreads();        // EQ + csum ready

        // ---- MMA (R8 layout: warp = 16 j x 64 s) ----
        float acc[8][4] = {};
        #pragma unroll
        for (int ks = 0; ks < 4; ks++) {
            const uint32_t aoff = SW((16 * wm + lr) * 128 + ks * 32 + lcs * 16);
            uint32_t ah[4];
            ldmx4(ah, sb + aoff);
            #pragma unroll
            for (int nb = 0; nb < 4; nb++) {
                const uint32_t boff = SW((ks * 16 + lr) * 128 + (nb * 16 + lcs * 8) * 2);
                uint32_t bh[4];
                ldmx4t(bh, sb + C_EQ + wn * 8192 + boff);
                mma16816(acc[2 * nb], ah, bh[0], bh[1]);
                mma16816(acc[2 * nb + 1], ah, bh[2], bh[3]);
            }
        }

        // ---- epilogue ----
        #pragma unroll
        for (int nt = 0; nt < 8; nt++) {
            const int sl = wn * 64 + nt * 8 + 2 * tig;
            const float2 cs = *(const float2*)&csum[sl];
            const float ix = __frcp_rn(cs.x), iy = __frcp_rn(cs.y);
            const int j = 16 * wm + g8;
            const size_t ob = ((size_t)h * D + j) * S
                            + (size_t)stp * (C_TPC * C_ST) + (size_t)t * C_ST + sl;
            float2 v0 = {acc[nt][0] * ix, acc[nt][1] * iy};
            float2 v1 = {acc[nt][2] * ix, acc[nt][3] * iy};
            *(float2*)(O + ob) = v0;
            *(float2*)(O + ob + 8 * S) = v1;
        }
        __syncthreads();        // MMA/epilogue done before EQ overwrite
    }
}

// =====================================================================
extern "C" void kernel_launch(void* const* d_in, const int* in_sizes, int n_in,
                              void* d_out, int out_size) {
    const float* q = (const float*)d_in[0];
    const float* k = (const float*)d_in[1];
    const float* v = (const float*)d_in[2];
    float* o = (float*)d_out;

    const int smemB = B_SRS + 256;        // 33024
    const int smemC = C_SINV + 256;       // 26880
    cudaFuncSetAttribute(kernelB, cudaFuncAttributeMaxDynamicSharedMemorySize, smemB);
    cudaFuncSetAttribute(kernelC, cudaFuncAttributeMaxDynamicSharedMemorySize, smemC);

    dim3 gridB(CHUNKS, HEADS);
    kernelB<<<gridB, 256, smemB>>>(k, v);
    dim3 gridC(C_CTAS_PER_HEAD, HEADS);
    kernelC<<<gridC, 256, smemC>>>(q, o);
}

// round 15
// speedup vs baseline: 1.4513x; 1.0580x over previous
#include <cuda_runtime.h>
#include <cuda_fp16.h>
#include <cstdint>

#define HEADS 32
#define D 64
#define S 8192

#define CHUNKS 16
#define CH_S (S / CHUNKS)   // 512
#define SUBS 64
#define B_NIT (CH_S / SUBS) // 8
#define C_ST 128
#define C_TPC 4
#define C_CTAS_PER_HEAD (S / (C_TPC * C_ST))   // 16

// ---------------- scratch ----------------
// Zero-initialized at module load; kernelC re-zeroes after consumption,
// so every launch (first call and graph replays) sees zeros.
__device__ __align__(16) float g_ctx_acc[HEADS * D * D];    // 512 KB accumulators
__device__ __align__(16) float g_rsum_acc[HEADS * D];
__device__ int g_cnt[HEADS];                                // per-head arrival counters

// ---------------- helpers ----------------
__device__ __forceinline__ uint32_t smem_u32(const void* p) {
    uint32_t a;
    asm("{ .reg .u64 t; cvta.to.shared.u64 t, %1; cvt.u32.u64 %0, t; }" : "=r"(a) : "l"(p));
    return a;
}
#define SW(o) ((uint32_t)(o) ^ ((((uint32_t)(o)) >> 3) & 0x70))

__device__ __forceinline__ void ldmx4(uint32_t* r, uint32_t addr) {
    asm volatile("ldmatrix.sync.aligned.m8n8.x4.shared.b16 {%0,%1,%2,%3}, [%4];"
                 : "=r"(r[0]), "=r"(r[1]), "=r"(r[2]), "=r"(r[3]) : "r"(addr));
}
__device__ __forceinline__ void ldmx4t(uint32_t* r, uint32_t addr) {
    asm volatile("ldmatrix.sync.aligned.m8n8.x4.trans.shared.b16 {%0,%1,%2,%3}, [%4];"
                 : "=r"(r[0]), "=r"(r[1]), "=r"(r[2]), "=r"(r[3]) : "r"(addr));
}
__device__ __forceinline__ void mma16816(float* c, const uint32_t* a,
                                         uint32_t b0, uint32_t b1) {
    asm volatile(
        "mma.sync.aligned.m16n8k16.row.col.f32.f16.f16.f32 "
        "{%0,%1,%2,%3}, {%4,%5,%6,%7}, {%8,%9}, {%0,%1,%2,%3};"
        : "+f"(c[0]), "+f"(c[1]), "+f"(c[2]), "+f"(c[3])
        : "r"(a[0]), "r"(a[1]), "r"(a[2]), "r"(a[3]), "r"(b0), "r"(b1));
}
__device__ __forceinline__ uint32_t hf2(float x, float y) {
    uint32_t d;
    asm("cvt.rn.f16x2.f32 %0, %1, %2;" : "=r"(d) : "f"(y), "f"(x));
    return d;
}
__device__ __forceinline__ uint2 pack4(float a, float b, float c, float d) {
    uint2 r;
    r.x = hf2(a, b);
    r.y = hf2(c, d);
    return r;
}

// =====================================================================
// Kernel B: per (head, chunk=512s): acc[i][j] += sum_s eK[i,s] V[j,s]
// fp16, double-buffered, DIRECT-LDG transform (no reg-prefetch arrays ->
// fits 64 regs -> 4 CTAs/SM -> grid 512 = single wave).
// Epilogue: atomicAdd into g_ctx_acc / g_rsum_acc (L2-resident).
// =====================================================================
#define B_SRS 32768
__global__ void __launch_bounds__(256, 4) kernelB(const float* __restrict__ K,
                                                  const float* __restrict__ V) {
    extern __shared__ __align__(1024) char sm[];
    const uint32_t sb = smem_u32(sm);
    float* sRS = (float*)(sm + B_SRS);
    const int tid = threadIdx.x, lane = tid & 31, wid = tid >> 5;
    const int ch = blockIdx.x, h = blockIdx.y;

    if (tid < 64) sRS[tid] = 0.f;

    const size_t gbase = (size_t)h * D * S + (size_t)ch * CH_S;
    const int wm = wid & 3, wn = wid >> 2;
    const int lr = (lane & 7) + ((lane >> 3) & 1) * 8;
    const int lcs = lane >> 4;

    // fixed per-thread load geometry (4 float4 per tensor per subtile)
    const int r0 = tid >> 4;              // rows r0, r0+16, r0+32, r0+48
    const int c4 = tid & 15;
    const float* kbase = K + gbase + (size_t)r0 * S + c4 * 4;
    const float* vbase = V + gbase + (size_t)r0 * S + c4 * 4;
    const uint32_t so0 = SW(r0 * 128 + c4 * 8);

    float rs[4] = {0.f, 0.f, 0.f, 0.f};

    auto transform = [&](int t, uint32_t bb) {
        const int off = t * SUBS;
        float4 kv[4], vv[4];
        #pragma unroll
        for (int u = 0; u < 4; u++) {
            kv[u] = *(const float4*)(kbase + (size_t)(16 * u) * S + off);
            vv[u] = *(const float4*)(vbase + (size_t)(16 * u) * S + off);
        }
        #pragma unroll
        for (int u = 0; u < 4; u++) {
            const uint32_t so = SW((r0 + 16 * u) * 128 + c4 * 8);
            float e0 = __expf(kv[u].x), e1 = __expf(kv[u].y);
            float e2 = __expf(kv[u].z), e3 = __expf(kv[u].w);
            rs[u] += (e0 + e1) + (e2 + e3);
            *(uint2*)(sm + bb + so) = pack4(e0, e1, e2, e3);
            *(uint2*)(sm + bb + 8192 + so) = pack4(vv[u].x, vv[u].y, vv[u].z, vv[u].w);
        }
    };

    __syncthreads();            // sRS init visible before end-of-kernel atomics
    transform(0, 0);

    float acc[4][4] = {};

    for (int t = 0; t < B_NIT; t++) {
        __syncthreads();        // buf[t&1] filled; MMA(t-1) reads drained
        const uint32_t bb = (uint32_t)(t & 1) * 16384;
        #pragma unroll
        for (int ks = 0; ks < 4; ks++) {
            const uint32_t aoff = SW((16 * wm + lr) * 128 + ks * 32 + lcs * 16);
            uint32_t ah[4];
            ldmx4(ah, sb + bb + aoff);
            uint32_t bh[2][4];
            #pragma unroll
            for (int hlf = 0; hlf < 2; hlf++) {
                const uint32_t boff =
                    SW((32 * wn + 16 * hlf + lr) * 128 + ks * 32 + lcs * 16);
                ldmx4(bh[hlf], sb + bb + 8192 + boff);
            }
            #pragma unroll
            for (int nt = 0; nt < 4; nt++) {
                const int hf = nt >> 1, sub = nt & 1;
                mma16816(acc[nt], ah, bh[hf][sub], bh[hf][sub + 2]);
            }
        }
        if (t + 1 < B_NIT) transform(t + 1, (uint32_t)((t + 1) & 1) * 16384);
    }

    #pragma unroll
    for (int u = 0; u < 4; u++) {
        float v = rs[u];
        v += __shfl_xor_sync(~0u, v, 1);
        v += __shfl_xor_sync(~0u, v, 2);
        v += __shfl_xor_sync(~0u, v, 4);
        v += __shfl_xor_sync(~0u, v, 8);
        if ((lane & 15) == 0) atomicAdd(&sRS[r0 + 16 * u], v);
    }
    __syncthreads();

    if (tid < 64) atomicAdd(&g_rsum_acc[h * D + tid], sRS[tid]);

    float* pc = g_ctx_acc + (size_t)h * (D * D);
    const int g8 = lane >> 2, tig = lane & 3;
    #pragma unroll
    for (int nt = 0; nt < 4; nt++) {
        const int j = 32 * wn + 8 * nt + 2 * tig;
        const int i0 = 16 * wm + g8;
        atomicAdd(&pc[i0 * D + j], acc[nt][0]);
        atomicAdd(&pc[i0 * D + j + 1], acc[nt][1]);
        atomicAdd(&pc[(i0 + 8) * D + j], acc[nt][2]);
        atomicAdd(&pc[(i0 + 8) * D + j + 1], acc[nt][3]);
    }
}

// =====================================================================
// Kernel C: per (head, 4 s-tiles): out[j,s] = colinv[s]*sum_i ctxT[j,i]*EQ[i,s]
// Prologue: normalize g_ctx_acc -> fp16 ctx^T in smem (absorbed B2).
// Self-cleaning: last CTA per head re-zeroes accumulators + counter.
// Mainloop = proven R8 tiling (warp = 16 j x 64 s). 64-reg cap -> 4 CTAs/SM.
// smem: ctx @0 (8K) | EQ @8K (16K) | csum[4][128] @24K | sinv @26624
// =====================================================================
#define C_EQ 8192
#define C_CS 24576
#define C_SINV 26624
__global__ void __launch_bounds__(256, 4) kernelC(const float* __restrict__ Q,
                                                  float* __restrict__ O) {
    extern __shared__ __align__(1024) char sm[];
    __shared__ int zflag;
    const uint32_t sb = smem_u32(sm);
    const int tid = threadIdx.x, lane = tid & 31, wid = tid >> 5;
    const int stp = blockIdx.x, h = blockIdx.y;

    float* sinv = (float*)(sm + C_SINV);
    if (tid < 64) sinv[tid] = 0.125f / g_rsum_acc[h * D + tid];
    if (tid < 128)
        ((float4*)(sm + C_CS))[tid] = make_float4(0.f, 0.f, 0.f, 0.f);
    __syncthreads();            // sinv + csum visible

    // normalize ctx_acc -> fp16 ctx^T smem tile (swizzled, 128B rows of 64 i)
    {
        const int j40 = (tid & 15) * 4;     // 4 consecutive j per thread
        const int ib = tid >> 4;            // i base 0..15
        #pragma unroll
        for (int k = 0; k < 4; k++) {
            const int i = ib + 16 * k;
            float4 v = *(const float4*)(g_ctx_acc + (size_t)h * (D * D) + i * D + j40);
            const float s = sinv[i];
            *(__half*)(sm + SW((j40 + 0) * 128 + i * 2)) = __float2half_rn(v.x * s);
            *(__half*)(sm + SW((j40 + 1) * 128 + i * 2)) = __float2half_rn(v.y * s);
            *(__half*)(sm + SW((j40 + 2) * 128 + i * 2)) = __float2half_rn(v.z * s);
            *(__half*)(sm + SW((j40 + 3) * 128 + i * 2)) = __float2half_rn(v.w * s);
        }
    }
    __syncthreads();            // ctx tile ready; this CTA's accumulator reads done

    // ---- self-cleaning: last CTA of this head zeroes the accumulators ----
    if (tid == 0) {
        const int old = atomicAdd(&g_cnt[h], 1);
        zflag = (old == C_CTAS_PER_HEAD - 1);
    }
    __syncthreads();
    if (zflag) {
        float4* pz = (float4*)(g_ctx_acc + (size_t)h * (D * D));
        #pragma unroll
        for (int u = 0; u < D * D / 4 / 256; u++)
            pz[tid + u * 256] = make_float4(0.f, 0.f, 0.f, 0.f);
        if (tid < D / 4)
            ((float4*)(g_rsum_acc + h * D))[tid] = make_float4(0.f, 0.f, 0.f, 0.f);
        if (tid == 0) g_cnt[h] = 0;
    }

    const int s4 = tid & 31, iw = tid >> 5;
    const int tsel = s4 >> 4;
    const int srel = (s4 & 15) * 4;
    const float* qt = Q + (size_t)h * D * S + (size_t)stp * (C_TPC * C_ST)
                    + (size_t)iw * S + s4 * 4;

    const int wm = wid & 3, wn = wid >> 2;
    const int lr = (lane & 7) + ((lane >> 3) & 1) * 8;
    const int lcs = lane >> 4;
    const int g8 = lane >> 2, tig = lane & 3;

    for (int t = 0; t < C_TPC; t++) {
        // ---- transform: direct LDG -> exp -> STS, csum in regs ----
        float* csum = (float*)(sm + C_CS) + t * 128;
        {
            float cs0 = 0.f, cs1 = 0.f, cs2 = 0.f, cs3 = 0.f;
            const float* qb = qt + t * C_ST;
            #pragma unroll
            for (int u = 0; u < 8; u++) {
                float4 qv = *(const float4*)(qb + (size_t)(8 * u) * S);
                float e0 = __expf(qv.x), e1 = __expf(qv.y);
                float e2 = __expf(qv.z), e3 = __expf(qv.w);
                cs0 += e0; cs1 += e1; cs2 += e2; cs3 += e3;
                const int i = iw + 8 * u;
                *(uint2*)(sm + C_EQ + tsel * 8192 + SW(i * 128 + srel * 2)) =
                    pack4(e0, e1, e2, e3);
            }
            atomicAdd(&csum[s4 * 4 + 0], cs0);
            atomicAdd(&csum[s4 * 4 + 1], cs1);
            atomicAdd(&csum[s4 * 4 + 2], cs2);
            atomicAdd(&csum[s4 * 4 + 3], cs3);
        }
        __syncthreads();        // EQ + csum ready

        // ---- MMA (R8 layout: warp = 16 j x 64 s) ----
        float acc[8][4] = {};
        #pragma unroll
        for (int ks = 0; ks < 4; ks++) {
            const uint32_t aoff = SW((16 * wm + lr) * 128 + ks * 32 + lcs * 16);
            uint32_t ah[4];
            ldmx4(ah, sb + aoff);
            #pragma unroll
            for (int nb = 0; nb < 4; nb++) {
                const uint32_t boff = SW((ks * 16 + lr) * 128 + (nb * 16 + lcs * 8) * 2);
                uint32_t bh[4];
                ldmx4t(bh, sb + C_EQ + wn * 8192 + boff);
                mma16816(acc[2 * nb], ah, bh[0], bh[1]);
                mma16816(acc[2 * nb + 1], ah, bh[2], bh[3]);
            }
        }

        // ---- epilogue ----
        #pragma unroll
        for (int nt = 0; nt < 8; nt++) {
            const int sl = wn * 64 + nt * 8 + 2 * tig;
            const float2 cs = *(const float2*)&csum[sl];
            const float ix = __frcp_rn(cs.x), iy = __frcp_rn(cs.y);
            const int j = 16 * wm + g8;
            const size_t ob = ((size_t)h * D + j) * S
                            + (size_t)stp * (C_TPC * C_ST) + (size_t)t * C_ST + sl;
            float2 v0 = {acc[nt][0] * ix, acc[nt][1] * iy};
            float2 v1 = {acc[nt][2] * ix, acc[nt][3] * iy};
            *(float2*)(O + ob) = v0;
            *(float2*)(O + ob + 8 * S) = v1;
        }
        __syncthreads();        // MMA/epilogue done before EQ overwrite
    }
}

// =====================================================================
extern "C" void kernel_launch(void* const* d_in, const int* in_sizes, int n_in,
                              void* d_out, int out_size) {
    const float* q = (const float*)d_in[0];
    const float* k = (const float*)d_in[1];
    const float* v = (const float*)d_in[2];
    float* o = (float*)d_out;

    const int smemB = B_SRS + 256;        // 33024
    const int smemC = C_SINV + 256;       // 26880
    cudaFuncSetAttribute(kernelB, cudaFuncAttributeMaxDynamicSharedMemorySize, smemB);
    cudaFuncSetAttribute(kernelC, cudaFuncAttributeMaxDynamicSharedMemorySize, smemC);

    dim3 gridB(CHUNKS, HEADS);
    kernelB<<<gridB, 256, smemB>>>(k, v);
    dim3 gridC(C_CTAS_PER_HEAD, HEADS);
    kernelC<<<gridC, 256, smemC>>>(q, o);
}